// round 5
// baseline (speedup 1.0000x reference)
#include <cuda_runtime.h>

// TwoTowerModel: B=524288, EMB=64, tower [128,64], fp32.
// out[b] = cos( relu-MLP(user_table[user_ids[b]]), relu-MLP(item_table[item_ids[b]]) )
//
// R5 design (sm_103a):
//  - 512 threads / CTA (16 warps), TILE=128 rows, 1 CTA/SM (193 KB smem).
//  - k-pair packing: all GEMM operands stored in smem as float2 {k even, k odd}.
//    fma.rn.f32x2 accumulates even/odd-k partials in one packed register --
//    BOTH operands are natural 64-bit loads, zero dup movs. Epilogue adds halves.
//  - Warp = col group; 32 lanes cover all 128 rows (A loads conflict-free, no
//    duplication); B loads warp-uniform (broadcast).
//  - Both gathers issued up-front (one DRAM latency, MLP=8).
//  - vec outputs overwrite consumed X2 buffers; final normalize+dot.

#define NT 512
#define TILE 128

// floats: W1p 8192 | W2p 8192 | B1 128 | B2 64 | Xu 8192 | Xi 8192 | Ht 16384
#define SMEM_FLOATS (8192 + 8192 + 128 + 64 + 8192 + 8192 + 16384)

typedef unsigned long long ull_t;

__device__ __forceinline__ void fma2(ull_t& d, ull_t a, ull_t b) {
    asm("fma.rn.f32x2 %0, %1, %2, %0;" : "+l"(d) : "l"(a), "l"(b));
}
__device__ __forceinline__ float2 unpk(ull_t v) {
    float2 f;
    asm("mov.b64 {%0, %1}, %2;" : "=f"(f.x), "=f"(f.y) : "l"(v));
    return f;
}

// Stage weight matrix W[2M][COLS4*4] (k-major) into smem as interleaved k-pairs:
// dst(float2)[m][c] = { W[2m][c], W[2m+1][c] }.
template <int COLS4, int UNITS>
__device__ __forceinline__ void stage_pairs(float* dst, const float* W, int tid) {
    const float4* g = (const float4*)W;
    float4* d = (float4*)dst;
    #pragma unroll
    for (int t = 0; t < UNITS / NT; ++t) {
        const int u  = tid + t * NT;
        const int m  = u / COLS4;
        const int c4 = u % COLS4;
        const float4 a = g[(2 * m) * COLS4 + c4];
        const float4 b = g[(2 * m + 1) * COLS4 + c4];
        const int fi = (m * COLS4 * 4 + 4 * c4) >> 1;   // float4 index into dst
        d[fi]     = make_float4(a.x, b.x, a.y, b.y);
        d[fi + 1] = make_float4(a.z, b.z, a.w, b.w);
    }
}

// Layer 1: H[128r][128c] = relu(X @ W1 + b1).
// sX: float2[32 m][128 row]; sW1: float2[32 m][128 c]; out sHt: float2[64 m'][128 row]
// warp ty owns cols 8*ty..+7 (uniform B); lane tx owns rows 4*tx..+3.
__device__ __forceinline__ void layer1(const float* sX, const float* sW1,
                                       const float* sB1, float* sHt,
                                       int tx, int ty) {
    ull_t acc[4][8];
    #pragma unroll
    for (int p = 0; p < 4; ++p)
        #pragma unroll
        for (int j = 0; j < 8; ++j) acc[p][j] = 0ull;

    const char* xa = (const char*)sX + tx * 32;     // (4*tx float2) * 8B
    const char* wb = (const char*)sW1 + ty * 64;    // (8*ty float2) * 8B
    #pragma unroll 4
    for (int m = 0; m < 32; ++m) {
        const ulonglong2 A0 = *(const ulonglong2*)(xa + m * 1024);
        const ulonglong2 A1 = *(const ulonglong2*)(xa + m * 1024 + 16);
        const ulonglong2 B0 = *(const ulonglong2*)(wb + m * 1024);
        const ulonglong2 B1 = *(const ulonglong2*)(wb + m * 1024 + 16);
        const ulonglong2 B2 = *(const ulonglong2*)(wb + m * 1024 + 32);
        const ulonglong2 B3 = *(const ulonglong2*)(wb + m * 1024 + 48);
        const ull_t a[4] = {A0.x, A0.y, A1.x, A1.y};
        const ull_t b[8] = {B0.x, B0.y, B1.x, B1.y, B2.x, B2.y, B3.x, B3.y};
        #pragma unroll
        for (int p = 0; p < 4; ++p)
            #pragma unroll
            for (int j = 0; j < 8; ++j)
                fma2(acc[p][j], a[p], b[j]);
    }

    // epilogue: combine halves, +bias, relu; write col-pairs m'=4*ty+s
    #pragma unroll
    for (int s = 0; s < 4; ++s) {
        const float b0 = sB1[8 * ty + 2 * s];
        const float b1 = sB1[8 * ty + 2 * s + 1];
        float2 h[4];
        #pragma unroll
        for (int r = 0; r < 4; ++r) {
            const float2 e = unpk(acc[r][2 * s]);
            const float2 o = unpk(acc[r][2 * s + 1]);
            h[r] = make_float2(fmaxf(e.x + e.y + b0, 0.f),
                               fmaxf(o.x + o.y + b1, 0.f));
        }
        float4* d = (float4*)((char*)sHt + (4 * ty + s) * 1024 + tx * 32);
        d[0] = make_float4(h[0].x, h[0].y, h[1].x, h[1].y);
        d[1] = make_float4(h[2].x, h[2].y, h[3].x, h[3].y);
    }
}

// Layer 2: O[128r][64c] = relu(H @ W2 + b2), written as vec[c][row] (scalar).
// sHt: float2[64 m][128 row]; sW2: float2[64 m][64 c].
// warp: half = ty>>3 selects rows [half*64, +64); tc = ty&7 -> cols 8*tc..+7.
__device__ __forceinline__ void layer2(const float* sHt, const float* sW2,
                                       const float* sB2, float* vec,
                                       int tx, int ty) {
    const int half = ty >> 3;
    const int tc   = ty & 7;
    ull_t acc[2][8];
    #pragma unroll
    for (int p = 0; p < 2; ++p)
        #pragma unroll
        for (int j = 0; j < 8; ++j) acc[p][j] = 0ull;

    const char* ha = (const char*)sHt + half * 512 + tx * 16;  // rows half*64+2tx
    const char* wb = (const char*)sW2 + tc * 64;               // cols 8*tc (uniform)
    #pragma unroll 4
    for (int m = 0; m < 64; ++m) {
        const ulonglong2 A  = *(const ulonglong2*)(ha + m * 1024);
        const ulonglong2 B0 = *(const ulonglong2*)(wb + m * 512);
        const ulonglong2 B1 = *(const ulonglong2*)(wb + m * 512 + 16);
        const ulonglong2 B2 = *(const ulonglong2*)(wb + m * 512 + 32);
        const ulonglong2 B3 = *(const ulonglong2*)(wb + m * 512 + 48);
        const ull_t a[2] = {A.x, A.y};
        const ull_t b[8] = {B0.x, B0.y, B1.x, B1.y, B2.x, B2.y, B3.x, B3.y};
        #pragma unroll
        for (int p = 0; p < 2; ++p)
            #pragma unroll
            for (int j = 0; j < 8; ++j)
                fma2(acc[p][j], a[p], b[j]);
    }

    // epilogue: rows r0=half*64+2*tx, r1=r0+1; cols 8*tc+j; vec is [64][128] float
    #pragma unroll
    for (int j = 0; j < 8; ++j) {
        const float bias = sB2[8 * tc + j];
        const float2 e0 = unpk(acc[0][j]);
        const float2 e1 = unpk(acc[1][j]);
        const float2 v = make_float2(fmaxf(e0.x + e0.y + bias, 0.f),
                                     fmaxf(e1.x + e1.y + bias, 0.f));
        *(float2*)((char*)vec + (8 * tc + j) * 512 + half * 256 + tx * 8) = v;
    }
}

__global__ void __launch_bounds__(NT, 1)
tt_kernel(const int* __restrict__ user_ids, const int* __restrict__ item_ids,
          const float4* __restrict__ user_tab, const float4* __restrict__ item_tab,
          const float* __restrict__ uW1, const float* __restrict__ ub1,
          const float* __restrict__ uW2, const float* __restrict__ ub2,
          const float* __restrict__ iW1, const float* __restrict__ ib1,
          const float* __restrict__ iW2, const float* __restrict__ ib2,
          float* __restrict__ out, int B)
{
    extern __shared__ float sm[];
    float* sW1p = sm;                  // [32][128] float2 (k-paired W1)
    float* sW2p = sW1p + 8192;         // [64][64]  float2 (k-paired W2)
    float* sB1  = sW2p + 8192;         // [128]
    float* sB2  = sB1 + 128;           // [64]
    float* sXu  = sB2 + 64;            // [32][128] float2 -> later user vec [64][128] f32
    float* sXi  = sXu + 8192;          // [32][128] float2 -> later item vec
    float* sHt  = sXi + 8192;          // [64][128] float2

    const int tid  = threadIdx.x;
    const int tx   = tid & 31;
    const int ty   = tid >> 5;
    const int base = blockIdx.x * TILE;

    // ---- phase 0: both gathers + tower-0 weights ----
    {
        const int row = tid & 127;
        const int q   = tid >> 7;                 // quarter of the embedding
        const int r   = base + row;
        const int rc  = (r < B) ? r : (B - 1);
        const int uid = user_ids[rc];
        const int iid = item_ids[rc];
        float4 gu[4], gi[4];
        const float4* up = user_tab + (size_t)uid * 16 + q * 4;
        const float4* ip = item_tab + (size_t)iid * 16 + q * 4;
        #pragma unroll
        for (int s = 0; s < 4; ++s) gu[s] = up[s];
        #pragma unroll
        for (int s = 0; s < 4; ++s) gi[s] = ip[s];

        stage_pairs<32, 1024>(sW1p, uW1, tid);    // W1: 64k x 128c
        stage_pairs<16, 1024>(sW2p, uW2, tid);    // W2: 128k x 64c
        if (tid < 128)      sB1[tid] = ub1[tid];
        else if (tid < 192) sB2[tid - 128] = ub2[tid - 128];

        float2* xu = (float2*)sXu;
        float2* xi = (float2*)sXi;
        #pragma unroll
        for (int s = 0; s < 4; ++s) {
            const int m = q * 8 + 2 * s;          // k0 = q*16+4s -> pair index
            xu[m * 128 + row]       = make_float2(gu[s].x, gu[s].y);
            xu[(m + 1) * 128 + row] = make_float2(gu[s].z, gu[s].w);
            xi[m * 128 + row]       = make_float2(gi[s].x, gi[s].y);
            xi[(m + 1) * 128 + row] = make_float2(gi[s].z, gi[s].w);
        }
    }
    __syncthreads();

    // ---- tower 0 (user) ----
    layer1(sXu, sW1p, sB1, sHt, tx, ty);
    __syncthreads();
    layer2(sHt, sW2p, sB2, sXu /* user vec */, tx, ty);
    __syncthreads();

    // ---- stage tower-1 weights ----
    stage_pairs<32, 1024>(sW1p, iW1, tid);
    stage_pairs<16, 1024>(sW2p, iW2, tid);
    if (tid < 128)      sB1[tid] = ib1[tid];
    else if (tid < 192) sB2[tid - 128] = ib2[tid - 128];
    __syncthreads();

    // ---- tower 1 (item) ----
    layer1(sXi, sW1p, sB1, sHt, tx, ty);
    __syncthreads();
    layer2(sHt, sW2p, sB2, sXi /* item vec */, tx, ty);
    __syncthreads();

    // ---- normalize + dot ----
    if (tid < TILE) {
        const int r = base + tid;
        if (r < B) {
            float su = 0.f, si = 0.f, d = 0.f;
            #pragma unroll 8
            for (int c = 0; c < 64; ++c) {
                const float a = sXu[c * 128 + tid];
                const float b = sXi[c * 128 + tid];
                su = fmaf(a, a, su);
                si = fmaf(b, b, si);
                d  = fmaf(a, b, d);
            }
            const float nu = fmaxf(sqrtf(su), 1e-12f);
            const float ni = fmaxf(sqrtf(si), 1e-12f);
            out[r] = d / (nu * ni);
        }
    }
}

extern "C" void kernel_launch(void* const* d_in, const int* in_sizes, int n_in,
                              void* d_out, int out_size)
{
    const int*    user_ids = (const int*)d_in[0];
    const int*    item_ids = (const int*)d_in[1];
    const float4* utab     = (const float4*)d_in[2];
    const float4* itab     = (const float4*)d_in[3];
    const float*  uW1 = (const float*)d_in[4];
    const float*  ub1 = (const float*)d_in[5];
    const float*  uW2 = (const float*)d_in[6];
    const float*  ub2 = (const float*)d_in[7];
    const float*  iW1 = (const float*)d_in[8];
    const float*  ib1 = (const float*)d_in[9];
    const float*  iW2 = (const float*)d_in[10];
    const float*  ib2 = (const float*)d_in[11];
    float* out = (float*)d_out;

    const int B = in_sizes[0];
    const int smem_bytes = SMEM_FLOATS * (int)sizeof(float);   // 197376

    cudaFuncSetAttribute(tt_kernel, cudaFuncAttributeMaxDynamicSharedMemorySize,
                         smem_bytes);

    const int grid = (B + TILE - 1) / TILE;
    tt_kernel<<<grid, NT, smem_bytes>>>(
        user_ids, item_ids, utab, itab,
        uW1, ub1, uW2, ub2, iW1, ib1, iW2, ib2,
        out, B);
}

// round 8
// speedup vs baseline: 1.3475x; 1.3475x over previous
#include <cuda_runtime.h>
#include <cuda_bf16.h>
#include <cstdint>

// TwoTowerModel (sm_103a bench, PTX target sm_103 -> no tcgen05; use legacy
// mma.sync bf16 tensor path). B=524288, EMB=64, tower [128,64], fp32 out.
//
// Per block: 128 rows, 512 threads, 1 CTA/SM.
// fp32 GEMMs via bf16 2-term split, 3 MMAs/tile (Ah*Bh + Ah*Bl + Al*Bh),
// fp32 accumulation in mma.sync.m16n8k16.
// smem tiles bf16 hi/lo, padded row strides (conflict-free ldmatrix).
// User tower result kept in registers; item epilogue reduces norms/dot.

#define NT 512
#define TILE 128

#define XS 144      // 64 bf16 = 128B + 16 pad
#define HS 272      // 128 bf16 = 256B + 16 pad

#define OFF_XU_HI 0
#define OFF_XU_LO (OFF_XU_HI + 128 * XS)
#define OFF_XI_HI (OFF_XU_LO + 128 * XS)
#define OFF_XI_LO (OFF_XI_HI + 128 * XS)
#define OFF_W1_HI (OFF_XI_LO + 128 * XS)
#define OFF_W1_LO (OFF_W1_HI + 128 * XS)
#define OFF_W2_HI (OFF_W1_LO + 128 * XS)
#define OFF_W2_LO (OFF_W2_HI + 64 * HS)
#define OFF_H_HI  (OFF_W2_LO + 64 * HS)
#define OFF_H_LO  (OFF_H_HI + 128 * HS)
#define OFF_SU    (OFF_H_LO + 128 * HS)
#define OFF_SI    (OFF_SU + 1024)
#define OFF_DOT   (OFF_SI + 1024)
#define OFF_B1    (OFF_DOT + 1024)
#define OFF_B2    (OFF_B1 + 512)
#define SMEM_BYTES (OFF_B2 + 256)          // 218880

#define XD  (128 * XS)     // hi->lo delta for X and W1 tiles
#define W2D (64 * HS)      // hi->lo delta for W2
#define HD  (128 * HS)     // hi->lo delta for H

static __device__ __forceinline__ uint32_t s2u(const void* p) {
    uint32_t a;
    asm("{ .reg .u64 t; cvta.to.shared.u64 t, %1; cvt.u32.u64 %0, t; }" : "=r"(a) : "l"(p));
    return a;
}

static __device__ __forceinline__ uint32_t packbf(float lo_f, float hi_f) {
    uint32_t r;
    asm("cvt.rn.bf16x2.f32 %0, %1, %2;" : "=r"(r) : "f"(hi_f), "f"(lo_f));
    return r;
}
static __device__ __forceinline__ void split2(float x0, float x1, uint32_t& hi, uint32_t& lo) {
    const float h0 = __bfloat162float(__float2bfloat16(x0));
    const float h1 = __bfloat162float(__float2bfloat16(x1));
    hi = packbf(h0, h1);
    lo = packbf(x0 - h0, x1 - h1);
}
static __device__ __forceinline__ void split8(const float* x, uint4& hi, uint4& lo) {
    split2(x[0], x[1], hi.x, lo.x);
    split2(x[2], x[3], hi.y, lo.y);
    split2(x[4], x[5], hi.z, lo.z);
    split2(x[6], x[7], hi.w, lo.w);
}

static __device__ __forceinline__ void ldx4(uint32_t* r, uint32_t addr) {
    asm volatile("ldmatrix.sync.aligned.m8n8.x4.shared.b16 {%0,%1,%2,%3}, [%4];"
                 : "=r"(r[0]), "=r"(r[1]), "=r"(r[2]), "=r"(r[3]) : "r"(addr));
}
static __device__ __forceinline__ void mma_bf(float* c, const uint32_t* a, const uint32_t* b) {
    asm volatile("mma.sync.aligned.m16n8k16.row.col.f32.bf16.bf16.f32 "
                 "{%0,%1,%2,%3}, {%4,%5,%6,%7}, {%8,%9}, {%0,%1,%2,%3};"
                 : "+f"(c[0]), "+f"(c[1]), "+f"(c[2]), "+f"(c[3])
                 : "r"(a[0]), "r"(a[1]), "r"(a[2]), "r"(a[3]), "r"(b[0]), "r"(b[1]));
}

// stage transposed hi/lo bf16 weights + biases for one tower
static __device__ __forceinline__ void stage_weights(char* smem, int tid,
        const float* W1, const float* b1, const float* W2, const float* b2) {
    {   // W1 [64k][128n] -> W1t[n][k] hi/lo
        const int n = tid & 127, kg = tid >> 7, k0 = kg * 16;
        float v[16];
        #pragma unroll
        for (int j = 0; j < 16; ++j) v[j] = W1[(k0 + j) * 128 + n];
        uint4 h0, l0, h1, l1;
        split8(v, h0, l0); split8(v + 8, h1, l1);
        char* p = smem + OFF_W1_HI + n * XS + kg * 32;
        *(uint4*)p = h0; *(uint4*)(p + 16) = h1;
        *(uint4*)(p + XD) = l0; *(uint4*)(p + XD + 16) = l1;
    }
    {   // W2 [128k][64n] -> W2t[n][k] hi/lo
        const int n = tid & 63, kg = tid >> 6, k0 = kg * 16;
        float v[16];
        #pragma unroll
        for (int j = 0; j < 16; ++j) v[j] = W2[(k0 + j) * 64 + n];
        uint4 h0, l0, h1, l1;
        split8(v, h0, l0); split8(v + 8, h1, l1);
        char* p = smem + OFF_W2_HI + n * HS + kg * 32;
        *(uint4*)p = h0; *(uint4*)(p + 16) = h1;
        *(uint4*)(p + W2D) = l0; *(uint4*)(p + W2D + 16) = l1;
    }
    float* sB1 = (float*)(smem + OFF_B1);
    float* sB2 = (float*)(smem + OFF_B2);
    if (tid < 128)      sB1[tid] = b1[tid];
    else if (tid < 192) sB2[tid - 128] = b2[tid - 128];
}

__global__ void __launch_bounds__(NT, 1)
tt_kernel(const int* __restrict__ user_ids, const int* __restrict__ item_ids,
          const float4* __restrict__ user_tab, const float4* __restrict__ item_tab,
          const float* __restrict__ uW1, const float* __restrict__ ub1,
          const float* __restrict__ uW2, const float* __restrict__ ub2,
          const float* __restrict__ iW1, const float* __restrict__ ib1,
          const float* __restrict__ iW2, const float* __restrict__ ib2,
          float* __restrict__ out, int B)
{
    extern __shared__ char smem[];
    const uint32_t sb = s2u(smem);
    const int tid = threadIdx.x;
    const int w   = tid >> 5;
    const int lid = tid & 31;
    const int base = blockIdx.x * TILE;

    // lane-derived ldmatrix constants
    const int l15   = lid & 15;
    const int ahalf = (lid >> 4) * 16;                 // A k-half byte offset
    const int nB    = (lid & 7) + ((lid >> 4) & 1) * 8; // B n row within 16-tile pair
    const int kb8   = ((lid >> 3) & 1) * 16;            // B k-half byte offset
    const int mt = w & 7;        // m-tile (16 rows)
    const int nh = w >> 3;       // layer1: n-half (64 cols); layer2: n-quarter (32 cols)
    const int g = lid >> 2, q = lid & 3;
    const int r0 = 16 * mt + g;

    float* sB1 = (float*)(smem + OFF_B1);
    float* sB2 = (float*)(smem + OFF_B2);

    // ---- phase 0: both gathers + user weights ----
    {
        const int row = tid & 127, qq = tid >> 7;       // qq in 0..3
        const int r  = base + row;
        const int rc = (r < B) ? r : (B - 1);
        const int uid = user_ids[rc];
        const int iid = item_ids[rc];
        const float4* up = user_tab + (size_t)uid * 16 + qq * 4;
        const float4* ip = item_tab + (size_t)iid * 16 + qq * 4;
        float vu[16], vi[16];
        #pragma unroll
        for (int s = 0; s < 4; ++s) {
            const float4 a = up[s];
            vu[4*s] = a.x; vu[4*s+1] = a.y; vu[4*s+2] = a.z; vu[4*s+3] = a.w;
        }
        #pragma unroll
        for (int s = 0; s < 4; ++s) {
            const float4 a = ip[s];
            vi[4*s] = a.x; vi[4*s+1] = a.y; vi[4*s+2] = a.z; vi[4*s+3] = a.w;
        }
        uint4 h0, l0, h1, l1;
        split8(vu, h0, l0); split8(vu + 8, h1, l1);
        char* pu = smem + OFF_XU_HI + row * XS + qq * 32;
        *(uint4*)pu = h0; *(uint4*)(pu + 16) = h1;
        *(uint4*)(pu + XD) = l0; *(uint4*)(pu + XD + 16) = l1;
        split8(vi, h0, l0); split8(vi + 8, h1, l1);
        char* pi = smem + OFF_XI_HI + row * XS + qq * 32;
        *(uint4*)pi = h0; *(uint4*)(pi + 16) = h1;
        *(uint4*)(pi + XD) = l0; *(uint4*)(pi + XD + 16) = l1;

        stage_weights(smem, tid, uW1, ub1, uW2, ub2);
    }
    __syncthreads();

    float uo[4][4];   // user tower layer-2 output, lives across item tower

    #pragma unroll 1
    for (int tower = 0; tower < 2; ++tower) {
        if (tower == 1) {
            __syncthreads();   // user L2 reads of W2/sB2 done
            stage_weights(smem, tid, iW1, ib1, iW2, ib2);
            __syncthreads();
        }
        const uint32_t XHI = tower ? OFF_XI_HI : OFF_XU_HI;

        // ---- layer 1: C1[16 rows][64 cols] per warp ----
        float c1[8][4];
        #pragma unroll
        for (int t = 0; t < 8; ++t)
            #pragma unroll
            for (int s = 0; s < 4; ++s) c1[t][s] = 0.f;

        {
            const uint32_t aH = sb + XHI + (16 * mt + l15) * XS + ahalf;
            const uint32_t bB = sb + OFF_W1_HI + (nh * 64 + nB) * XS + kb8;
            #pragma unroll
            for (int ks = 0; ks < 4; ++ks) {
                uint32_t ah[4], al[4];
                ldx4(ah, aH + ks * 32);
                ldx4(al, aH + XD + ks * 32);
                #pragma unroll
                for (int p = 0; p < 4; ++p) {
                    uint32_t bh[4], bl[4];
                    const uint32_t ba = bB + p * (16 * XS) + ks * 32;
                    ldx4(bh, ba);
                    ldx4(bl, ba + XD);
                    mma_bf(c1[2*p],   ah, bh);
                    mma_bf(c1[2*p],   ah, bl);
                    mma_bf(c1[2*p],   al, bh);
                    mma_bf(c1[2*p+1], ah, bh + 2);
                    mma_bf(c1[2*p+1], ah, bl + 2);
                    mma_bf(c1[2*p+1], al, bh + 2);
                }
            }
        }

        // epilogue 1: bias+relu, split, store Ht hi/lo
        #pragma unroll
        for (int nt = 0; nt < 8; ++nt) {
            const int col = nh * 64 + nt * 8 + 2 * q;
            const float b0 = sB1[col], b1 = sB1[col + 1];
            uint32_t hi, lo;
            split2(fmaxf(c1[nt][0] + b0, 0.f), fmaxf(c1[nt][1] + b1, 0.f), hi, lo);
            char* p0 = smem + OFF_H_HI + r0 * HS + col * 2;
            *(uint32_t*)p0 = hi; *(uint32_t*)(p0 + HD) = lo;
            split2(fmaxf(c1[nt][2] + b0, 0.f), fmaxf(c1[nt][3] + b1, 0.f), hi, lo);
            char* p1 = smem + OFF_H_HI + (r0 + 8) * HS + col * 2;
            *(uint32_t*)p1 = hi; *(uint32_t*)(p1 + HD) = lo;
        }
        __syncthreads();

        // ---- layer 2: C2[16 rows][32 cols] per warp ----
        float c2[4][4];
        #pragma unroll
        for (int t = 0; t < 4; ++t)
            #pragma unroll
            for (int s = 0; s < 4; ++s) c2[t][s] = 0.f;

        {
            const uint32_t aH = sb + OFF_H_HI + (16 * mt + l15) * HS + ahalf;
            const uint32_t bB = sb + OFF_W2_HI + (nh * 32 + nB) * HS + kb8;
            #pragma unroll
            for (int ks = 0; ks < 8; ++ks) {
                uint32_t ah[4], al[4];
                ldx4(ah, aH + ks * 32);
                ldx4(al, aH + HD + ks * 32);
                #pragma unroll
                for (int p = 0; p < 2; ++p) {
                    uint32_t bh[4], bl[4];
                    const uint32_t ba = bB + p * (16 * HS) + ks * 32;
                    ldx4(bh, ba);
                    ldx4(bl, ba + W2D);
                    mma_bf(c2[2*p],   ah, bh);
                    mma_bf(c2[2*p],   ah, bl);
                    mma_bf(c2[2*p],   al, bh);
                    mma_bf(c2[2*p+1], ah, bh + 2);
                    mma_bf(c2[2*p+1], ah, bl + 2);
                    mma_bf(c2[2*p+1], al, bh + 2);
                }
            }
        }

        // epilogue 2: bias+relu
        float o[4][4];
        #pragma unroll
        for (int nt = 0; nt < 4; ++nt) {
            const int col = nh * 32 + nt * 8 + 2 * q;
            const float b0 = sB2[col], b1 = sB2[col + 1];
            o[nt][0] = fmaxf(c2[nt][0] + b0, 0.f);
            o[nt][1] = fmaxf(c2[nt][1] + b1, 0.f);
            o[nt][2] = fmaxf(c2[nt][2] + b0, 0.f);
            o[nt][3] = fmaxf(c2[nt][3] + b1, 0.f);
        }

        if (tower == 0) {
            #pragma unroll
            for (int nt = 0; nt < 4; ++nt)
                #pragma unroll
                for (int s = 0; s < 4; ++s) uo[nt][s] = o[nt][s];
        } else {
            float su0 = 0.f, su1 = 0.f, si0 = 0.f, si1 = 0.f, d0 = 0.f, d1 = 0.f;
            #pragma unroll
            for (int nt = 0; nt < 4; ++nt) {
                su0 = fmaf(uo[nt][0], uo[nt][0], fmaf(uo[nt][1], uo[nt][1], su0));
                si0 = fmaf(o[nt][0],  o[nt][0],  fmaf(o[nt][1],  o[nt][1],  si0));
                d0  = fmaf(uo[nt][0], o[nt][0],  fmaf(uo[nt][1], o[nt][1],  d0));
                su1 = fmaf(uo[nt][2], uo[nt][2], fmaf(uo[nt][3], uo[nt][3], su1));
                si1 = fmaf(o[nt][2],  o[nt][2],  fmaf(o[nt][3],  o[nt][3],  si1));
                d1  = fmaf(uo[nt][2], o[nt][2],  fmaf(uo[nt][3], o[nt][3],  d1));
            }
            #pragma unroll
            for (int m = 1; m <= 2; m <<= 1) {
                su0 += __shfl_xor_sync(0xffffffffu, su0, m);
                si0 += __shfl_xor_sync(0xffffffffu, si0, m);
                d0  += __shfl_xor_sync(0xffffffffu, d0,  m);
                su1 += __shfl_xor_sync(0xffffffffu, su1, m);
                si1 += __shfl_xor_sync(0xffffffffu, si1, m);
                d1  += __shfl_xor_sync(0xffffffffu, d1,  m);
            }
            if (q == 0) {
                float* sSU = (float*)(smem + OFF_SU);
                float* sSI = (float*)(smem + OFF_SI);
                float* sD  = (float*)(smem + OFF_DOT);
                const int i0 = r0 * 2 + nh;
                const int i1 = (r0 + 8) * 2 + nh;
                sSU[i0] = su0; sSI[i0] = si0; sD[i0] = d0;
                sSU[i1] = su1; sSI[i1] = si1; sD[i1] = d1;
            }
        }
    }
    __syncthreads();

    // ---- finalize ----
    if (tid < TILE) {
        const int r = base + tid;
        if (r < B) {
            const float* sSU = (const float*)(smem + OFF_SU);
            const float* sSI = (const float*)(smem + OFF_SI);
            const float* sD  = (const float*)(smem + OFF_DOT);
            const float su = sSU[2 * tid] + sSU[2 * tid + 1];
            const float si = sSI[2 * tid] + sSI[2 * tid + 1];
            const float d  = sD[2 * tid]  + sD[2 * tid + 1];
            const float nu = fmaxf(sqrtf(su), 1e-12f);
            const float ni = fmaxf(sqrtf(si), 1e-12f);
            out[r] = d / (nu * ni);
        }
    }
}

extern "C" void kernel_launch(void* const* d_in, const int* in_sizes, int n_in,
                              void* d_out, int out_size)
{
    const int*    user_ids = (const int*)d_in[0];
    const int*    item_ids = (const int*)d_in[1];
    const float4* utab     = (const float4*)d_in[2];
    const float4* itab     = (const float4*)d_in[3];
    const float*  uW1 = (const float*)d_in[4];
    const float*  ub1 = (const float*)d_in[5];
    const float*  uW2 = (const float*)d_in[6];
    const float*  ub2 = (const float*)d_in[7];
    const float*  iW1 = (const float*)d_in[8];
    const float*  ib1 = (const float*)d_in[9];
    const float*  iW2 = (const float*)d_in[10];
    const float*  ib2 = (const float*)d_in[11];
    float* out = (float*)d_out;

    const int B = in_sizes[0];

    cudaFuncSetAttribute(tt_kernel, cudaFuncAttributeMaxDynamicSharedMemorySize,
                         SMEM_BYTES);

    const int grid = (B + TILE - 1) / TILE;
    tt_kernel<<<grid, NT, SMEM_BYTES>>>(
        user_ids, item_ids, utab, itab,
        uW1, ub1, uW2, ub2, iW1, ib1, iW2, ib2,
        out, B);
}

// round 13
// speedup vs baseline: 2.1362x; 1.5853x over previous
#include <cuda_runtime.h>
#include <cuda_bf16.h>
#include <cstdint>

// TwoTowerModel (sm_103a, PTX target sm_103 -> legacy mma.sync bf16 path).
// B=524288, EMB=64, tower [128,64], fp32 out.
//
// R8: tower-parallel warps + register-resident H.
//  - 512 threads, 128 rows/block, 1 CTA/SM. Warps 0-7 user tower, 8-15 item.
//  - Each warp: 16 rows x full width, layer1+layer2 fused per 16-col chunk:
//    L1 accum (3-term bf16 MMA) -> bias/relu/split in regs -> directly the
//    A-fragment of L2's k16 step (C-frag layout == A-frag layout). No H tile,
//    no intermediate barriers. Only 2 __syncthreads in the kernel.
//  - All smem tiles bf16 hi/lo, XOR-swizzled (no padding).
//  - User warps publish vec to smem (row-stride 66 to dodge bank conflicts);
//    item warps compute norms + dot + output.

#define NT 512
#define TILE 128

#define OFF_X    0            // 4 tiles: XU_HI, XU_LO, XI_HI, XI_LO (16K each)
#define OFF_W1   65536        // W1U_HI, W1U_LO, W1I_HI, W1I_LO
#define OFF_W2   131072       // W2U_HI, W2U_LO, W2I_HI, W2I_LO
#define OFF_UVEC 196608       // 128 x 66 f32 = 33792
#define OFF_B1   230400       // 2 x 128 f32
#define OFF_B2   231424       // 2 x 64 f32
#define SMEM_BYTES 231936

#define TSZ 16384             // one bf16 tile (128x128B or 64x256B)

static __device__ __forceinline__ uint32_t s2u(const void* p) {
    uint32_t a;
    asm("{ .reg .u64 t; cvta.to.shared.u64 t, %1; cvt.u32.u64 %0, t; }" : "=r"(a) : "l"(p));
    return a;
}
// 128B-row tile swizzle (Swizzle<3,4,3>): bits[6:4] ^= bits[9:7]
static __device__ __forceinline__ uint32_t swzX(uint32_t o) { return o ^ ((o >> 3) & 0x70); }
// 256B-row tile swizzle: bits[7:4] ^= bits[11:8]
static __device__ __forceinline__ uint32_t swzW2(uint32_t o) { return o ^ ((o >> 4) & 0xF0); }

static __device__ __forceinline__ uint32_t packbf(float lo_f, float hi_f) {
    uint32_t r;
    asm("cvt.rn.bf16x2.f32 %0, %1, %2;" : "=r"(r) : "f"(hi_f), "f"(lo_f));
    return r;
}
static __device__ __forceinline__ void split2(float x0, float x1, uint32_t& hi, uint32_t& lo) {
    const float h0 = __bfloat162float(__float2bfloat16(x0));
    const float h1 = __bfloat162float(__float2bfloat16(x1));
    hi = packbf(h0, h1);
    lo = packbf(x0 - h0, x1 - h1);
}
static __device__ __forceinline__ void split8(const float* x, uint4& hi, uint4& lo) {
    split2(x[0], x[1], hi.x, lo.x);
    split2(x[2], x[3], hi.y, lo.y);
    split2(x[4], x[5], hi.z, lo.z);
    split2(x[6], x[7], hi.w, lo.w);
}

static __device__ __forceinline__ void ldx4(uint32_t* r, uint32_t addr) {
    asm volatile("ldmatrix.sync.aligned.m8n8.x4.shared.b16 {%0,%1,%2,%3}, [%4];"
                 : "=r"(r[0]), "=r"(r[1]), "=r"(r[2]), "=r"(r[3]) : "r"(addr));
}
static __device__ __forceinline__ void mma_bf(float* c, const uint32_t* a, const uint32_t* b) {
    asm volatile("mma.sync.aligned.m16n8k16.row.col.f32.bf16.bf16.f32 "
                 "{%0,%1,%2,%3}, {%4,%5,%6,%7}, {%8,%9}, {%0,%1,%2,%3};"
                 : "+f"(c[0]), "+f"(c[1]), "+f"(c[2]), "+f"(c[3])
                 : "r"(a[0]), "r"(a[1]), "r"(a[2]), "r"(a[3]), "r"(b[0]), "r"(b[1]));
}

__global__ void __launch_bounds__(NT, 1)
tt_kernel(const int* __restrict__ user_ids, const int* __restrict__ item_ids,
          const float4* __restrict__ user_tab, const float4* __restrict__ item_tab,
          const float* __restrict__ uW1, const float* __restrict__ ub1,
          const float* __restrict__ uW2, const float* __restrict__ ub2,
          const float* __restrict__ iW1, const float* __restrict__ ib1,
          const float* __restrict__ iW2, const float* __restrict__ ib2,
          float* __restrict__ out, int B)
{
    extern __shared__ char smem[];
    const uint32_t sb = s2u(smem);
    const int tid = threadIdx.x;
    const int w   = tid >> 5;
    const int lid = tid & 31;
    const int base = blockIdx.x * TILE;

    // ================= phase 0: gathers + both towers' weights =================
    {
        const int row = tid & 127, qq = tid >> 7;        // qq in 0..3 (k quarter)
        const int r  = base + row;
        const int rc = (r < B) ? r : (B - 1);
        const int uid = user_ids[rc];
        const int iid = item_ids[rc];
        const float4* up = user_tab + (size_t)uid * 16 + qq * 4;
        const float4* ip = item_tab + (size_t)iid * 16 + qq * 4;
        float vu[16], vi[16];
        #pragma unroll
        for (int s = 0; s < 4; ++s) {
            const float4 a = up[s];
            vu[4*s] = a.x; vu[4*s+1] = a.y; vu[4*s+2] = a.z; vu[4*s+3] = a.w;
        }
        #pragma unroll
        for (int s = 0; s < 4; ++s) {
            const float4 a = ip[s];
            vi[4*s] = a.x; vi[4*s+1] = a.y; vi[4*s+2] = a.z; vi[4*s+3] = a.w;
        }
        const uint32_t o0 = swzX((uint32_t)(row * 128 + qq * 32));
        const uint32_t o1 = swzX((uint32_t)(row * 128 + qq * 32 + 16));
        uint4 h0, l0, h1, l1;
        split8(vu, h0, l0); split8(vu + 8, h1, l1);
        *(uint4*)(smem + OFF_X + o0) = h0;
        *(uint4*)(smem + OFF_X + o1) = h1;
        *(uint4*)(smem + OFF_X + TSZ + o0) = l0;
        *(uint4*)(smem + OFF_X + TSZ + o1) = l1;
        split8(vi, h0, l0); split8(vi + 8, h1, l1);
        *(uint4*)(smem + OFF_X + 2*TSZ + o0) = h0;
        *(uint4*)(smem + OFF_X + 2*TSZ + o1) = h1;
        *(uint4*)(smem + OFF_X + 3*TSZ + o0) = l0;
        *(uint4*)(smem + OFF_X + 3*TSZ + o1) = l1;

        // W1: 1024 units (tower x 128n x 4 kgroups of 16)
        #pragma unroll
        for (int t = 0; t < 2; ++t) {
            const int u = tid + t * NT;
            const int tw = u >> 9, n = u & 127, kg = (u >> 7) & 3, k0 = kg * 16;
            const float* W1 = tw ? iW1 : uW1;
            float v[16];
            #pragma unroll
            for (int j = 0; j < 16; ++j) v[j] = W1[(k0 + j) * 128 + n];
            uint4 hh0, ll0, hh1, ll1;
            split8(v, hh0, ll0); split8(v + 8, hh1, ll1);
            const uint32_t p0 = swzX((uint32_t)(n * 128 + kg * 32));
            const uint32_t p1 = swzX((uint32_t)(n * 128 + kg * 32 + 16));
            char* bh = smem + OFF_W1 + tw * (2 * TSZ);
            *(uint4*)(bh + p0) = hh0; *(uint4*)(bh + p1) = hh1;
            *(uint4*)(bh + TSZ + p0) = ll0; *(uint4*)(bh + TSZ + p1) = ll1;
        }
        // W2: 1024 units (tower x 64n x 8 kgroups of 16)
        #pragma unroll
        for (int t = 0; t < 2; ++t) {
            const int u = tid + t * NT;
            const int tw = u >> 9, n = u & 63, kg = (u >> 6) & 7, k0 = kg * 16;
            const float* W2 = tw ? iW2 : uW2;
            float v[16];
            #pragma unroll
            for (int j = 0; j < 16; ++j) v[j] = W2[(k0 + j) * 64 + n];
            uint4 hh0, ll0, hh1, ll1;
            split8(v, hh0, ll0); split8(v + 8, hh1, ll1);
            const uint32_t p0 = swzW2((uint32_t)(n * 256 + kg * 32));
            const uint32_t p1 = swzW2((uint32_t)(n * 256 + kg * 32 + 16));
            char* bh = smem + OFF_W2 + tw * (2 * TSZ);
            *(uint4*)(bh + p0) = hh0; *(uint4*)(bh + p1) = hh1;
            *(uint4*)(bh + TSZ + p0) = ll0; *(uint4*)(bh + TSZ + p1) = ll1;
        }
        float* B1s = (float*)(smem + OFF_B1);
        float* B2s = (float*)(smem + OFF_B2);
        if (tid < 128)      B1s[tid] = ub1[tid];
        else if (tid < 256) B1s[tid] = ib1[tid - 128];
        else if (tid < 320) B2s[tid - 256] = ub2[tid - 256];
        else if (tid < 384) B2s[tid - 256] = ib2[tid - 320];
    }
    __syncthreads();

    // ================= MMA phase: warp = (tower, 16 rows) =================
    const int tower = w >> 3;            // 0 = user, 1 = item
    const int mt    = w & 7;             // 16-row tile
    const int g = lid >> 2, q = lid & 3;
    const int l15   = lid & 15;
    const int ahalf = (lid >> 4) * 16;
    const int nB    = (lid & 7) + ((lid >> 4) & 1) * 8;
    const int kb8   = ((lid >> 3) & 1) * 16;

    const uint32_t XHI  = sb + OFF_X  + tower * (2 * TSZ);
    const uint32_t W1HI = sb + OFF_W1 + tower * (2 * TSZ);
    const uint32_t W2HI = sb + OFF_W2 + tower * (2 * TSZ);
    const float* sB1 = (const float*)(smem + OFF_B1) + tower * 128;
    const float* sB2 = (const float*)(smem + OFF_B2) + tower * 64;

    // preload X A-fragments (k=64: 4 k16 steps), hi and lo
    uint32_t xh[4][4], xl[4][4];
    {
        const int arow = 16 * mt + l15;
        #pragma unroll
        for (int ks = 0; ks < 4; ++ks) {
            const uint32_t o = swzX((uint32_t)(arow * 128 + ks * 32 + ahalf));
            ldx4(xh[ks], XHI + o);
            ldx4(xl[ks], XHI + TSZ + o);
        }
    }

    float c2[8][4];
    #pragma unroll
    for (int f = 0; f < 8; ++f)
        #pragma unroll
        for (int s = 0; s < 4; ++s) c2[f][s] = 0.f;

    #pragma unroll
    for (int chunk = 0; chunk < 8; ++chunk) {
        // ---- layer 1, cols [chunk*16, chunk*16+16) ----
        float c1[2][4];
        #pragma unroll
        for (int s = 0; s < 4; ++s) { c1[0][s] = 0.f; c1[1][s] = 0.f; }
        #pragma unroll
        for (int ks = 0; ks < 4; ++ks) {
            const uint32_t o = swzX((uint32_t)((chunk * 16 + nB) * 128 + ks * 32 + kb8));
            uint32_t bh[4], bl[4];
            ldx4(bh, W1HI + o);
            ldx4(bl, W1HI + TSZ + o);
            mma_bf(c1[0], xh[ks], bh);
            mma_bf(c1[0], xh[ks], bl);
            mma_bf(c1[0], xl[ks], bh);
            mma_bf(c1[1], xh[ks], bh + 2);
            mma_bf(c1[1], xh[ks], bl + 2);
            mma_bf(c1[1], xl[ks], bh + 2);
        }
        // bias + relu + split -> L2 A-fragment for this k16 step (in registers)
        const int col0 = chunk * 16 + 2 * q;
        const float b0 = sB1[col0], b1 = sB1[col0 + 1];
        const float b2v = sB1[col0 + 8], b3v = sB1[col0 + 9];
        uint32_t a2h[4], a2l[4];
        split2(fmaxf(c1[0][0] + b0,  0.f), fmaxf(c1[0][1] + b1,  0.f), a2h[0], a2l[0]);
        split2(fmaxf(c1[0][2] + b0,  0.f), fmaxf(c1[0][3] + b1,  0.f), a2h[1], a2l[1]);
        split2(fmaxf(c1[1][0] + b2v, 0.f), fmaxf(c1[1][1] + b3v, 0.f), a2h[2], a2l[2]);
        split2(fmaxf(c1[1][2] + b2v, 0.f), fmaxf(c1[1][3] + b3v, 0.f), a2h[3], a2l[3]);
        // ---- layer 2, k16 step = chunk, all 64 cols ----
        #pragma unroll
        for (int p = 0; p < 4; ++p) {
            const uint32_t o2 = swzW2((uint32_t)((p * 16 + nB) * 256 + chunk * 32 + kb8));
            uint32_t wh[4], wl[4];
            ldx4(wh, W2HI + o2);
            ldx4(wl, W2HI + TSZ + o2);
            mma_bf(c2[2*p],     a2h, wh);
            mma_bf(c2[2*p],     a2h, wl);
            mma_bf(c2[2*p],     a2l, wh);
            mma_bf(c2[2*p + 1], a2h, wh + 2);
            mma_bf(c2[2*p + 1], a2h, wl + 2);
            mma_bf(c2[2*p + 1], a2l, wh + 2);
        }
    }

    // ================= epilogue =================
    // o[f][s]: rows {16mt+g, 16mt+g+8}, cols f*8 + {2q, 2q+1}
    #pragma unroll
    for (int f = 0; f < 8; ++f) {
        const float bb0 = sB2[f * 8 + 2 * q], bb1 = sB2[f * 8 + 2 * q + 1];
        c2[f][0] = fmaxf(c2[f][0] + bb0, 0.f);
        c2[f][1] = fmaxf(c2[f][1] + bb1, 0.f);
        c2[f][2] = fmaxf(c2[f][2] + bb0, 0.f);
        c2[f][3] = fmaxf(c2[f][3] + bb1, 0.f);
    }
    const int r0 = 16 * mt + g, r1 = r0 + 8;
    float* uv = (float*)(smem + OFF_UVEC);
    if (tower == 0) {
        #pragma unroll
        for (int f = 0; f < 8; ++f) {
            *(float2*)(uv + r0 * 66 + f * 8 + 2 * q) = make_float2(c2[f][0], c2[f][1]);
            *(float2*)(uv + r1 * 66 + f * 8 + 2 * q) = make_float2(c2[f][2], c2[f][3]);
        }
    }
    __syncthreads();
    if (tower == 1) {
        float su0 = 0.f, si0 = 0.f, d0 = 0.f, su1 = 0.f, si1 = 0.f, d1 = 0.f;
        #pragma unroll
        for (int f = 0; f < 8; ++f) {
            const float2 u0 = *(const float2*)(uv + r0 * 66 + f * 8 + 2 * q);
            const float2 u1 = *(const float2*)(uv + r1 * 66 + f * 8 + 2 * q);
            su0 = fmaf(u0.x, u0.x, fmaf(u0.y, u0.y, su0));
            si0 = fmaf(c2[f][0], c2[f][0], fmaf(c2[f][1], c2[f][1], si0));
            d0  = fmaf(u0.x, c2[f][0], fmaf(u0.y, c2[f][1], d0));
            su1 = fmaf(u1.x, u1.x, fmaf(u1.y, u1.y, su1));
            si1 = fmaf(c2[f][2], c2[f][2], fmaf(c2[f][3], c2[f][3], si1));
            d1  = fmaf(u1.x, c2[f][2], fmaf(u1.y, c2[f][3], d1));
        }
        #pragma unroll
        for (int m = 1; m <= 2; m <<= 1) {
            su0 += __shfl_xor_sync(0xffffffffu, su0, m);
            si0 += __shfl_xor_sync(0xffffffffu, si0, m);
            d0  += __shfl_xor_sync(0xffffffffu, d0,  m);
            su1 += __shfl_xor_sync(0xffffffffu, su1, m);
            si1 += __shfl_xor_sync(0xffffffffu, si1, m);
            d1  += __shfl_xor_sync(0xffffffffu, d1,  m);
        }
        if (q == 0) {
            const int ra = base + r0, rb = base + r1;
            if (ra < B)
                out[ra] = d0 / (fmaxf(sqrtf(su0), 1e-12f) * fmaxf(sqrtf(si0), 1e-12f));
            if (rb < B)
                out[rb] = d1 / (fmaxf(sqrtf(su1), 1e-12f) * fmaxf(sqrtf(si1), 1e-12f));
        }
    }
}

extern "C" void kernel_launch(void* const* d_in, const int* in_sizes, int n_in,
                              void* d_out, int out_size)
{
    const int*    user_ids = (const int*)d_in[0];
    const int*    item_ids = (const int*)d_in[1];
    const float4* utab     = (const float4*)d_in[2];
    const float4* itab     = (const float4*)d_in[3];
    const float*  uW1 = (const float*)d_in[4];
    const float*  ub1 = (const float*)d_in[5];
    const float*  uW2 = (const float*)d_in[6];
    const float*  ub2 = (const float*)d_in[7];
    const float*  iW1 = (const float*)d_in[8];
    const float*  ib1 = (const float*)d_in[9];
    const float*  iW2 = (const float*)d_in[10];
    const float*  ib2 = (const float*)d_in[11];
    float* out = (float*)d_out;

    const int B = in_sizes[0];

    cudaFuncSetAttribute(tt_kernel, cudaFuncAttributeMaxDynamicSharedMemorySize,
                         SMEM_BYTES);

    const int grid = (B + TILE - 1) / TILE;
    tt_kernel<<<grid, NT, SMEM_BYTES>>>(
        user_ids, item_ids, utab, itab,
        uW1, ub1, uW2, ub2, iW1, ib1, iW2, ib2,
        out, B);
}